// round 7
// baseline (speedup 1.0000x reference)
#include <cuda_runtime.h>
#include <math.h>
#include <stdint.h>

#define N_TOKENS 16384
#define D_MODEL  4096
#define N_EXP    64
#define LB_COEF  0.01f

#define KC     64                 // k per stage (two 32-k warpgroup halves)
#define NCHUNK (D_MODEL / KC)     // 64
#define TM     128
#define NCTA   (N_TOKENS / TM)    // 128
#define NTHR   512

// stage layout (float indices); 64 k-values per row + 4 pad => pitch 68
#define PITCH   68
#define A_HI    0
#define A_LO    (128 * PITCH)                // 8704
#define B_HI    (2 * 128 * PITCH)            // 17408
#define B_LO    (B_HI + 64 * PITCH)          // 21760
#define STAGE_F (B_LO + 64 * PITCH)          // 26112 floats = 104448 B
#define DYN_BYTES (2 * STAGE_F * 4)          // 208896 B

// ---------------- helpers ----------------
static __device__ __forceinline__ uint32_t tf32_of(float f) {
    uint32_t r;
    asm("cvt.rna.tf32.f32 %0, %1;" : "=r"(r) : "f"(f));
    return r;
}

static __device__ __forceinline__ void cvt4(float4 v, uint4& h, uint4& l) {
    h.x = tf32_of(v.x); h.y = tf32_of(v.y); h.z = tf32_of(v.z); h.w = tf32_of(v.w);
    l.x = tf32_of(v.x - __uint_as_float(h.x));
    l.y = tf32_of(v.y - __uint_as_float(h.y));
    l.z = tf32_of(v.z - __uint_as_float(h.z));
    l.w = tf32_of(v.w - __uint_as_float(h.w));
}

#define MMA(d, a, b)                                                     \
    asm volatile(                                                        \
        "mma.sync.aligned.m16n8k8.row.col.f32.tf32.tf32.f32 "            \
        "{%0,%1,%2,%3}, {%4,%5,%6,%7}, {%8,%9}, {%0,%1,%2,%3};"          \
        : "+f"((d)[0]), "+f"((d)[1]), "+f"((d)[2]), "+f"((d)[3])         \
        : "r"((a)[0]), "r"((a)[1]), "r"((a)[2]), "r"((a)[3]),            \
          "r"((b)[0]), "r"((b)[1]))

// ---------------- device scratch (zero-initialized at module load) ----------------
__device__ float g_psum[N_EXP];
__device__ int   g_cnt[N_EXP];
__device__ int   g_ticket;

// ---------------- fused GEMM (3xTF32, K-split warpgroups) + softmax/top2 + loss --
// 512 threads = 16 warps. CTA tile 128x64. Warp tile 32x32 (mi=2, ni=4).
// Warpgroup 0 (wid 0-7): k[0,32) of each stage; warpgroup 1 (wid 8-15): k[32,64).
__global__ __launch_bounds__(NTHR, 1)
void router_kernel(const float* __restrict__ x,
                   const float* __restrict__ gw,
                   float* __restrict__ out)
{
    extern __shared__ float dynsm[];
    __shared__ int   cb[N_EXP];
    __shared__ float s_red[N_EXP];
    __shared__ float s_m[TM];
    __shared__ float s_inv[TM];
    __shared__ int   s_islast;

    const int tid  = threadIdx.x;
    const int t0   = blockIdx.x * TM;
    const int lane = tid & 31;
    const int wid  = tid >> 5;
    const int wg   = wid >> 3;          // k-half
    const int widg = wid & 7;
    const int wm   = widg >> 1;         // 0..3 -> token base wm*32
    const int wn   = widg & 1;          // 0..1 -> expert base wn*32
    const int lr   = lane >> 2;
    const int lc   = lane & 3;
    const int kofs = wg * 32;           // k offset within stage

    uint32_t* sm = (uint32_t*)dynsm;

    if (tid < N_EXP) cb[tid] = 0;

    // fill mapping: R = row 0..63, g = f4 slot (loads g and g+8 of 16 per row)
    const int R = tid >> 3;
    const int g = tid & 7;

    const float4* x4 = (const float4*)x;     // row pitch 1024 f4
    const float4* w4 = (const float4*)gw;

    const size_t xo0 = (size_t)(t0 + R)      * 1024 + g;   // +8 for second f4
    const size_t xo1 = (size_t)(t0 + R + 64) * 1024 + g;
    const size_t wo  = (size_t)R             * 1024 + g;

    float4 pa[4], pb[2];

    // ---- prologue: load + convert + store chunk 0 (16 f4 per row per chunk)
    pa[0] = x4[xo0]; pa[1] = x4[xo0 + 8];
    pa[2] = x4[xo1]; pa[3] = x4[xo1 + 8];
    pb[0] = w4[wo];  pb[1] = w4[wo + 8];
    {
        uint32_t* s = sm;
        uint4 h, l;
        cvt4(pa[0], h, l);
        *(uint4*)(s + A_HI + R * PITCH + 4 * g) = h;
        *(uint4*)(s + A_LO + R * PITCH + 4 * g) = l;
        cvt4(pa[1], h, l);
        *(uint4*)(s + A_HI + R * PITCH + 4 * g + 32) = h;
        *(uint4*)(s + A_LO + R * PITCH + 4 * g + 32) = l;
        cvt4(pa[2], h, l);
        *(uint4*)(s + A_HI + (R + 64) * PITCH + 4 * g) = h;
        *(uint4*)(s + A_LO + (R + 64) * PITCH + 4 * g) = l;
        cvt4(pa[3], h, l);
        *(uint4*)(s + A_HI + (R + 64) * PITCH + 4 * g + 32) = h;
        *(uint4*)(s + A_LO + (R + 64) * PITCH + 4 * g + 32) = l;
        cvt4(pb[0], h, l);
        *(uint4*)(s + B_HI + R * PITCH + 4 * g) = h;
        *(uint4*)(s + B_LO + R * PITCH + 4 * g) = l;
        cvt4(pb[1], h, l);
        *(uint4*)(s + B_HI + R * PITCH + 4 * g + 32) = h;
        *(uint4*)(s + B_LO + R * PITCH + 4 * g + 32) = l;
    }
    __syncthreads();

    float acc[2][4][4];
#pragma unroll
    for (int mi = 0; mi < 2; mi++)
#pragma unroll
        for (int ni = 0; ni < 4; ni++)
#pragma unroll
            for (int j = 0; j < 4; j++) acc[mi][ni][j] = 0.0f;

    // ---- main loop: double-buffered, one bar per 64-k chunk
    for (int c = 0; c < NCHUNK; c++) {
        if (c + 1 < NCHUNK) {
            const size_t d = (size_t)(c + 1) * 16;
            pa[0] = x4[xo0 + d]; pa[1] = x4[xo0 + d + 8];
            pa[2] = x4[xo1 + d]; pa[3] = x4[xo1 + d + 8];
            pb[0] = w4[wo + d];  pb[1] = w4[wo + d + 8];
        }

        const uint32_t* s = sm + (c & 1) * STAGE_F;
#pragma unroll
        for (int ks = 0; ks < 4; ks++) {
            const int kc = kofs + ks * 8 + lc;
            uint32_t ah[2][4], al[2][4];
#pragma unroll
            for (int mi = 0; mi < 2; mi++) {
                int base = (wm * 32 + mi * 16 + lr) * PITCH + kc;
                ah[mi][0] = s[A_HI + base];
                ah[mi][1] = s[A_HI + base + 8 * PITCH];
                ah[mi][2] = s[A_HI + base + 4];
                ah[mi][3] = s[A_HI + base + 8 * PITCH + 4];
                al[mi][0] = s[A_LO + base];
                al[mi][1] = s[A_LO + base + 8 * PITCH];
                al[mi][2] = s[A_LO + base + 4];
                al[mi][3] = s[A_LO + base + 8 * PITCH + 4];
            }
#pragma unroll
            for (int ni = 0; ni < 4; ni++) {
                int bb = (wn * 32 + ni * 8 + lr) * PITCH + kc;
                uint32_t bh[2] = { s[B_HI + bb], s[B_HI + bb + 4] };
                uint32_t bl[2] = { s[B_LO + bb], s[B_LO + bb + 4] };
#pragma unroll
                for (int mi = 0; mi < 2; mi++) {
                    MMA(acc[mi][ni], ah[mi], bh);
                    MMA(acc[mi][ni], al[mi], bh);
                    MMA(acc[mi][ni], ah[mi], bl);
                }
            }
        }

        if (c + 1 < NCHUNK) {
            uint32_t* d = sm + ((c + 1) & 1) * STAGE_F;
            uint4 h, l;
            cvt4(pa[0], h, l);
            *(uint4*)(d + A_HI + R * PITCH + 4 * g) = h;
            *(uint4*)(d + A_LO + R * PITCH + 4 * g) = l;
            cvt4(pa[1], h, l);
            *(uint4*)(d + A_HI + R * PITCH + 4 * g + 32) = h;
            *(uint4*)(d + A_LO + R * PITCH + 4 * g + 32) = l;
            cvt4(pa[2], h, l);
            *(uint4*)(d + A_HI + (R + 64) * PITCH + 4 * g) = h;
            *(uint4*)(d + A_LO + (R + 64) * PITCH + 4 * g) = l;
            cvt4(pa[3], h, l);
            *(uint4*)(d + A_HI + (R + 64) * PITCH + 4 * g + 32) = h;
            *(uint4*)(d + A_LO + (R + 64) * PITCH + 4 * g + 32) = l;
            cvt4(pb[0], h, l);
            *(uint4*)(d + B_HI + R * PITCH + 4 * g) = h;
            *(uint4*)(d + B_LO + R * PITCH + 4 * g) = l;
            cvt4(pb[1], h, l);
            *(uint4*)(d + B_HI + R * PITCH + 4 * g + 32) = h;
            *(uint4*)(d + B_LO + R * PITCH + 4 * g + 32) = l;
        }
        __syncthreads();
    }

    // ---- merge warpgroup accumulators into G[128][65] (overlays stage smem)
    float* G = dynsm;
    if (wg == 0) {
#pragma unroll
        for (int mi = 0; mi < 2; mi++)
#pragma unroll
            for (int ni = 0; ni < 4; ni++) {
                int tr = wm * 32 + mi * 16 + lr;
                int ec = wn * 32 + ni * 8 + 2 * lc;
                G[tr * 65 + ec]           = acc[mi][ni][0];
                G[tr * 65 + ec + 1]       = acc[mi][ni][1];
                G[(tr + 8) * 65 + ec]     = acc[mi][ni][2];
                G[(tr + 8) * 65 + ec + 1] = acc[mi][ni][3];
            }
    }
    __syncthreads();
    if (wg == 1) {
#pragma unroll
        for (int mi = 0; mi < 2; mi++)
#pragma unroll
            for (int ni = 0; ni < 4; ni++) {
                int tr = wm * 32 + mi * 16 + lr;
                int ec = wn * 32 + ni * 8 + 2 * lc;
                G[tr * 65 + ec]           += acc[mi][ni][0];
                G[tr * 65 + ec + 1]       += acc[mi][ni][1];
                G[(tr + 8) * 65 + ec]     += acc[mi][ni][2];
                G[(tr + 8) * 65 + ec + 1] += acc[mi][ni][3];
            }
    }
    __syncthreads();

    // ---- epilogue phase 1: per-token max + top2 on logits (no MUFU)
    int   i1 = 0, i2 = 0;
    float v1 = 0.f, v2 = 0.f;
    if (tid < TM) {
        const float* row = G + tid * 65;
        float m = row[0];
        v1 = -INFINITY; v2 = -INFINITY;
#pragma unroll 8
        for (int e = 0; e < N_EXP; e++) {
            float v = row[e];
            m = fmaxf(m, v);
            if (v > v1)      { v2 = v1; i2 = i1; v1 = v; i1 = e; }
            else if (v > v2) { v2 = v;  i2 = e; }
        }
        s_m[tid] = m;
    }
    __syncthreads();

    // ---- phase 2: all 512 threads exponentiate (parallel MUFU)
#pragma unroll
    for (int i = 0; i < (TM * N_EXP) / NTHR; i++) {
        int idx = tid + i * NTHR;
        int t = idx >> 6, e = idx & 63;
        G[t * 65 + e] = expf(G[t * 65 + e] - s_m[t]);
    }
    __syncthreads();

    // ---- phase 3: per-token sums + outputs
    if (tid < TM) {
        const float* row = G + tid * 65;
        float ssum = 0.0f;
#pragma unroll 8
        for (int e = 0; e < N_EXP; e++) ssum += row[e];
        s_inv[tid] = 1.0f / ssum;

        float e1 = row[i1], e2 = row[i2];
        float rn = 1.0f / (e1 + e2);
        int tg = t0 + tid;
        out[2 * tg]     = e1 * rn;
        out[2 * tg + 1] = e2 * rn;
        out[2 * N_TOKENS + 2 * tg]     = (float)i1;
        out[2 * N_TOKENS + 2 * tg + 1] = (float)i2;
        atomicAdd(&cb[i1], 1);
    }
    __syncthreads();

    // ---- phase 4: per-expert prob sums -> global
    if (tid < N_EXP) {
        float s = 0.0f;
#pragma unroll 8
        for (int t = 0; t < TM; t++) s += G[t * 65 + tid] * s_inv[t];
        atomicAdd(&g_psum[tid], s);
        atomicAdd(&g_cnt[tid], cb[tid]);
    }

    // ---- last CTA: loss + scratch reset
    if (tid == 0) {
        __threadfence();
        int t = atomicAdd(&g_ticket, 1);
        s_islast = (t == NCTA - 1) ? 1 : 0;
    }
    __syncthreads();
    if (s_islast) {
        __threadfence();
        if (tid < N_EXP) {
            float p = *(volatile float*)&g_psum[tid];
            int   f = *(volatile int*)&g_cnt[tid];
            s_red[tid] = (float)f * p;
            g_psum[tid] = 0.0f;
            g_cnt[tid]  = 0;
        }
        __syncthreads();
        for (int st = 32; st > 0; st >>= 1) {
            if (tid < st) s_red[tid] += s_red[tid + st];
            __syncthreads();
        }
        if (tid == 0) {
            out[4 * N_TOKENS] = LB_COEF * s_red[0] * (1.0f / N_TOKENS) * (1.0f / N_TOKENS);
            g_ticket = 0;
        }
    }
}

// ---------------- launch ----------------
extern "C" void kernel_launch(void* const* d_in, const int* in_sizes, int n_in,
                              void* d_out, int out_size)
{
    const float* x  = (const float*)d_in[0];
    const float* gw = (const float*)d_in[1];
    float* out = (float*)d_out;

    cudaFuncSetAttribute(router_kernel,
                         cudaFuncAttributeMaxDynamicSharedMemorySize, DYN_BYTES);

    router_kernel<<<NCTA, NTHR, DYN_BYTES>>>(x, gw, out);
}

// round 8
// speedup vs baseline: 1.2100x; 1.2100x over previous
#include <cuda_runtime.h>
#include <math.h>
#include <stdint.h>

#define N_TOKENS 16384
#define D_MODEL  4096
#define N_EXP    64
#define LB_COEF  0.01f

#define KC     64                 // k per stage (two 32-k warpgroup halves)
#define NCHUNK (D_MODEL / KC)     // 64
#define TM     128
#define NCTA   (N_TOKENS / TM)    // 128
#define NTHR   512
#define NSTAGE 4

// stage layout (float indices): raw fp32, rows of 64 k + 4 pad => pitch 68
#define PITCH   68
#define B_OFF   (128 * PITCH)                // B region after 128 A rows
#define STAGE_F ((128 + 64) * PITCH)         // 13056 floats = 52224 B
#define DYN_BYTES (NSTAGE * STAGE_F * 4)     // 208896 B

#define TFMASK 0xFFFFE000u

// ---------------- helpers ----------------
static __device__ __forceinline__ uint32_t smem_u32(const void* p) {
    uint32_t a;
    asm("{ .reg .u64 t; cvta.to.shared.u64 t, %1; cvt.u32.u64 %0, t; }" : "=r"(a) : "l"(p));
    return a;
}

#define CPASYNC16(dst, src) \
    asm volatile("cp.async.cg.shared.global [%0], [%1], 16;" :: "r"(dst), "l"(src))
#define CPCOMMIT()  asm volatile("cp.async.commit_group;" ::: "memory")
#define CPWAIT2()   asm volatile("cp.async.wait_group 2;" ::: "memory")

#define MMA(d, a, b)                                                     \
    asm volatile(                                                        \
        "mma.sync.aligned.m16n8k8.row.col.f32.tf32.tf32.f32 "            \
        "{%0,%1,%2,%3}, {%4,%5,%6,%7}, {%8,%9}, {%0,%1,%2,%3};"          \
        : "+f"((d)[0]), "+f"((d)[1]), "+f"((d)[2]), "+f"((d)[3])         \
        : "r"((a)[0]), "r"((a)[1]), "r"((a)[2]), "r"((a)[3]),            \
          "r"((b)[0]), "r"((b)[1]))

// split: hi = truncate-to-tf32 (exact), lo = x - hi (exact fp32)
#define SPLIT(r, h, l) do {                                              \
    (h) = (r) & TFMASK;                                                  \
    (l) = __float_as_uint(__uint_as_float(r) - __uint_as_float(h));      \
} while (0)

// ---------------- device scratch (zero-initialized at module load) ----------------
__device__ float g_psum[N_EXP];
__device__ int   g_cnt[N_EXP];
__device__ int   g_ticket;

// ---------------- fused GEMM (3xTF32, cp.async pipeline) + softmax/top2 + loss ----
// 512 threads = 16 warps. CTA tile 128x64. Warp tile 32x32 (mi=2, ni=4).
// Warpgroup 0 (wid 0-7): k[0,32) of each stage; warpgroup 1: k[32,64).
__global__ __launch_bounds__(NTHR, 1)
void router_kernel(const float* __restrict__ x,
                   const float* __restrict__ gw,
                   float* __restrict__ out)
{
    extern __shared__ float dynsm[];
    __shared__ int   cb[N_EXP];
    __shared__ float s_red[N_EXP];
    __shared__ float s_m[TM];
    __shared__ float s_inv[TM];
    __shared__ int   s_islast;

    const int tid  = threadIdx.x;
    const int t0   = blockIdx.x * TM;
    const int lane = tid & 31;
    const int wid  = tid >> 5;
    const int wg   = wid >> 3;
    const int widg = wid & 7;
    const int wm   = widg >> 1;         // 0..3 -> token base wm*32
    const int wn   = widg & 1;          // 0..1 -> expert base wn*32
    const int lr   = lane >> 2;
    const int lc   = lane & 3;
    const int kofs = wg * 32;

    if (tid < N_EXP) cb[tid] = 0;

    const uint32_t sbase = smem_u32(dynsm);

    // per-thread fill slots: A 4 x 16B, B 2 x 16B
    int  rowA[4], slotA[4], rowB[2], slotB[2];
    const float* srcA[4];
    const float* srcB[2];
#pragma unroll
    for (int i = 0; i < 4; i++) {
        int idx = i * NTHR + tid;           // 0..2047
        rowA[i] = idx >> 4; slotA[i] = idx & 15;
        srcA[i] = x + (size_t)(t0 + rowA[i]) * D_MODEL + slotA[i] * 4;
    }
#pragma unroll
    for (int i = 0; i < 2; i++) {
        int idx = i * NTHR + tid;           // 0..1023
        rowB[i] = idx >> 4; slotB[i] = idx & 15;
        srcB[i] = gw + (size_t)rowB[i] * D_MODEL + slotB[i] * 4;
    }

    // ---- prologue: issue fills for chunks 0..2
#pragma unroll
    for (int c = 0; c < 3; c++) {
        const uint32_t st = sbase + (uint32_t)(c * STAGE_F * 4);
#pragma unroll
        for (int i = 0; i < 4; i++)
            CPASYNC16(st + (uint32_t)((rowA[i] * PITCH + slotA[i] * 4) * 4),
                      srcA[i] + (size_t)c * KC);
#pragma unroll
        for (int i = 0; i < 2; i++)
            CPASYNC16(st + (uint32_t)((B_OFF + rowB[i] * PITCH + slotB[i] * 4) * 4),
                      srcB[i] + (size_t)c * KC);
        CPCOMMIT();
    }

    float acc[2][4][4];
#pragma unroll
    for (int mi = 0; mi < 2; mi++)
#pragma unroll
        for (int ni = 0; ni < 4; ni++)
#pragma unroll
            for (int j = 0; j < 4; j++) acc[mi][ni][j] = 0.0f;

    // ---- main loop
    for (int c = 0; c < NCHUNK; c++) {
        CPWAIT2();                 // fill(c) complete (2 younger groups pending)
        __syncthreads();           // all warps past compute(c-1); data visible

        // issue fill(c+3) into buffer (c+3)%4 = (c-1)%4 (readers done)
        if (c + 3 < NCHUNK) {
            const uint32_t st = sbase + (uint32_t)(((c + 3) & 3) * STAGE_F * 4);
#pragma unroll
            for (int i = 0; i < 4; i++)
                CPASYNC16(st + (uint32_t)((rowA[i] * PITCH + slotA[i] * 4) * 4),
                          srcA[i] + (size_t)(c + 3) * KC);
#pragma unroll
            for (int i = 0; i < 2; i++)
                CPASYNC16(st + (uint32_t)((B_OFF + rowB[i] * PITCH + slotB[i] * 4) * 4),
                          srcB[i] + (size_t)(c + 3) * KC);
        }
        CPCOMMIT();                // unconditional: keeps pending-count invariant

        const uint32_t* su = (const uint32_t*)(dynsm + (c & 3) * STAGE_F);
#pragma unroll
        for (int ks = 0; ks < 4; ks++) {
            const int kc = kofs + ks * 8 + lc;
            uint32_t ah[2][4], al[2][4];
#pragma unroll
            for (int mi = 0; mi < 2; mi++) {
                int base = (wm * 32 + mi * 16 + lr) * PITCH + kc;
                uint32_t r0 = su[base];
                uint32_t r1 = su[base + 8 * PITCH];
                uint32_t r2 = su[base + 4];
                uint32_t r3 = su[base + 8 * PITCH + 4];
                SPLIT(r0, ah[mi][0], al[mi][0]);
                SPLIT(r1, ah[mi][1], al[mi][1]);
                SPLIT(r2, ah[mi][2], al[mi][2]);
                SPLIT(r3, ah[mi][3], al[mi][3]);
            }
#pragma unroll
            for (int ni = 0; ni < 4; ni++) {
                int bb = B_OFF + (wn * 32 + ni * 8 + lr) * PITCH + kc;
                uint32_t q0 = su[bb], q1 = su[bb + 4];
                uint32_t bh[2], bl[2];
                SPLIT(q0, bh[0], bl[0]);
                SPLIT(q1, bh[1], bl[1]);
#pragma unroll
                for (int mi = 0; mi < 2; mi++) {
                    MMA(acc[mi][ni], ah[mi], bh);
                    MMA(acc[mi][ni], al[mi], bh);
                    MMA(acc[mi][ni], ah[mi], bl);
                }
            }
        }
    }
    __syncthreads();   // all compute done before overlaying G

    // ---- merge warpgroup accumulators into G[128][65] (overlays stage smem)
    float* G = dynsm;
    if (wg == 0) {
#pragma unroll
        for (int mi = 0; mi < 2; mi++)
#pragma unroll
            for (int ni = 0; ni < 4; ni++) {
                int tr = wm * 32 + mi * 16 + lr;
                int ec = wn * 32 + ni * 8 + 2 * lc;
                G[tr * 65 + ec]           = acc[mi][ni][0];
                G[tr * 65 + ec + 1]       = acc[mi][ni][1];
                G[(tr + 8) * 65 + ec]     = acc[mi][ni][2];
                G[(tr + 8) * 65 + ec + 1] = acc[mi][ni][3];
            }
    }
    __syncthreads();
    if (wg == 1) {
#pragma unroll
        for (int mi = 0; mi < 2; mi++)
#pragma unroll
            for (int ni = 0; ni < 4; ni++) {
                int tr = wm * 32 + mi * 16 + lr;
                int ec = wn * 32 + ni * 8 + 2 * lc;
                G[tr * 65 + ec]           += acc[mi][ni][0];
                G[tr * 65 + ec + 1]       += acc[mi][ni][1];
                G[(tr + 8) * 65 + ec]     += acc[mi][ni][2];
                G[(tr + 8) * 65 + ec + 1] += acc[mi][ni][3];
            }
    }
    __syncthreads();

    // ---- epilogue phase 1: per-token max + top2 on logits
    int   i1 = 0, i2 = 0;
    if (tid < TM) {
        const float* row = G + tid * 65;
        float v1 = -INFINITY, v2 = -INFINITY;
#pragma unroll 8
        for (int e = 0; e < N_EXP; e++) {
            float v = row[e];
            if (v > v1)      { v2 = v1; i2 = i1; v1 = v; i1 = e; }
            else if (v > v2) { v2 = v;  i2 = e; }
        }
        s_m[tid] = v1;   // max == top1
    }
    __syncthreads();

    // ---- phase 2: all 512 threads exponentiate (parallel MUFU)
#pragma unroll
    for (int i = 0; i < (TM * N_EXP) / NTHR; i++) {
        int idx = tid + i * NTHR;
        int t = idx >> 6, e = idx & 63;
        G[t * 65 + e] = expf(G[t * 65 + e] - s_m[t]);
    }
    __syncthreads();

    // ---- phase 3: per-token sums + outputs
    if (tid < TM) {
        const float* row = G + tid * 65;
        float ssum = 0.0f;
#pragma unroll 8
        for (int e = 0; e < N_EXP; e++) ssum += row[e];
        s_inv[tid] = 1.0f / ssum;

        float e1 = row[i1], e2 = row[i2];
        float rn = 1.0f / (e1 + e2);
        int tg = t0 + tid;
        out[2 * tg]     = e1 * rn;
        out[2 * tg + 1] = e2 * rn;
        out[2 * N_TOKENS + 2 * tg]     = (float)i1;
        out[2 * N_TOKENS + 2 * tg + 1] = (float)i2;
        atomicAdd(&cb[i1], 1);
    }
    __syncthreads();

    // ---- phase 4: per-expert prob sums -> global
    if (tid < N_EXP) {
        float s = 0.0f;
#pragma unroll 8
        for (int t = 0; t < TM; t++) s += G[t * 65 + tid] * s_inv[t];
        atomicAdd(&g_psum[tid], s);
        atomicAdd(&g_cnt[tid], cb[tid]);
    }

    // ---- last CTA: loss + scratch reset
    if (tid == 0) {
        __threadfence();
        int t = atomicAdd(&g_ticket, 1);
        s_islast = (t == NCTA - 1) ? 1 : 0;
    }
    __syncthreads();
    if (s_islast) {
        __threadfence();
        if (tid < N_EXP) {
            float p = *(volatile float*)&g_psum[tid];
            int   f = *(volatile int*)&g_cnt[tid];
            s_red[tid] = (float)f * p;
            g_psum[tid] = 0.0f;
            g_cnt[tid]  = 0;
        }
        __syncthreads();
        for (int st = 32; st > 0; st >>= 1) {
            if (tid < st) s_red[tid] += s_red[tid + st];
            __syncthreads();
        }
        if (tid == 0) {
            out[4 * N_TOKENS] = LB_COEF * s_red[0] * (1.0f / N_TOKENS) * (1.0f / N_TOKENS);
            g_ticket = 0;
        }
    }
}

// ---------------- launch ----------------
extern "C" void kernel_launch(void* const* d_in, const int* in_sizes, int n_in,
                              void* d_out, int out_size)
{
    const float* x  = (const float*)d_in[0];
    const float* gw = (const float*)d_in[1];
    float* out = (float*)d_out;

    cudaFuncSetAttribute(router_kernel,
                         cudaFuncAttributeMaxDynamicSharedMemorySize, DYN_BYTES);

    router_kernel<<<NCTA, NTHR, DYN_BYTES>>>(x, gw, out);
}

// round 9
// speedup vs baseline: 1.2112x; 1.0009x over previous
#include <cuda_runtime.h>
#include <math.h>
#include <stdint.h>

#define N_TOKENS 16384
#define D_MODEL  4096
#define N_EXP    64
#define LB_COEF  0.01f

#define KC     32                 // k per stage (two 16-k warpgroup halves)
#define NCHUNK (D_MODEL / KC)     // 128
#define TM     64
#define NCTA   (N_TOKENS / TM)    // 256
#define NTHR   256
#define NSTAGE 4

// stage layout (float indices): raw fp32, rows of 32 k + 4 pad => pitch 36
#define PITCH   36
#define B_OFF   (64 * PITCH)                 // B region after 64 A rows
#define STAGE_F ((64 + 64) * PITCH)          // 4608 floats = 18432 B
#define DYN_BYTES (NSTAGE * STAGE_F * 4)     // 73728 B

#define TFMASK 0xFFFFE000u

// ---------------- helpers ----------------
static __device__ __forceinline__ uint32_t smem_u32(const void* p) {
    uint32_t a;
    asm("{ .reg .u64 t; cvta.to.shared.u64 t, %1; cvt.u32.u64 %0, t; }" : "=r"(a) : "l"(p));
    return a;
}

#define CPASYNC16(dst, src) \
    asm volatile("cp.async.cg.shared.global [%0], [%1], 16;" :: "r"(dst), "l"(src))
#define CPCOMMIT()  asm volatile("cp.async.commit_group;" ::: "memory")
#define CPWAIT2()   asm volatile("cp.async.wait_group 2;" ::: "memory")

#define MMA(d, a, b)                                                     \
    asm volatile(                                                        \
        "mma.sync.aligned.m16n8k8.row.col.f32.tf32.tf32.f32 "            \
        "{%0,%1,%2,%3}, {%4,%5,%6,%7}, {%8,%9}, {%0,%1,%2,%3};"          \
        : "+f"((d)[0]), "+f"((d)[1]), "+f"((d)[2]), "+f"((d)[3])         \
        : "r"((a)[0]), "r"((a)[1]), "r"((a)[2]), "r"((a)[3]),            \
          "r"((b)[0]), "r"((b)[1]))

// split: hi = truncate-to-tf32 (exact), lo = x - hi (exact fp32)
#define SPLIT(r, h, l) do {                                              \
    (h) = (r) & TFMASK;                                                  \
    (l) = __float_as_uint(__uint_as_float(r) - __uint_as_float(h));      \
} while (0)

// ---------------- device scratch (zero-initialized at module load) ----------------
__device__ float g_psum[N_EXP];
__device__ int   g_cnt[N_EXP];
__device__ int   g_ticket;

// ---------------- fused GEMM (3xTF32, cp.async pipeline) + softmax/top2 + loss ----
// 256 threads = 8 warps, 2 CTAs/SM. CTA tile 64x64. Warp tile 32x32 (mi=2, ni=4).
// Warpgroup 0 (wid 0-3): k[0,16) of each stage; warpgroup 1 (wid 4-7): k[16,32).
__global__ __launch_bounds__(NTHR, 2)
void router_kernel(const float* __restrict__ x,
                   const float* __restrict__ gw,
                   float* __restrict__ out)
{
    extern __shared__ float dynsm[];
    __shared__ int   cb[N_EXP];
    __shared__ float s_red[N_EXP];
    __shared__ float s_m[TM];
    __shared__ float s_inv[TM];
    __shared__ int   s_islast;

    const int tid  = threadIdx.x;
    const int t0   = blockIdx.x * TM;
    const int lane = tid & 31;
    const int wid  = tid >> 5;
    const int wg   = wid >> 2;          // k-half
    const int widg = wid & 3;
    const int wm   = widg >> 1;         // 0..1 -> token base wm*32
    const int wn   = widg & 1;          // 0..1 -> expert base wn*32
    const int lr   = lane >> 2;
    const int lc   = lane & 3;
    const int kofs = wg * 16;           // k offset within 32-k stage

    if (tid < N_EXP) cb[tid] = 0;

    const uint32_t sbase = smem_u32(dynsm);

    // per-thread fill slots: A 2 x 16B, B 2 x 16B (64 rows x 8 f4 each)
    int  rowA[2], slotA[2], rowB[2], slotB[2];
    const float* srcA[2];
    const float* srcB[2];
#pragma unroll
    for (int i = 0; i < 2; i++) {
        int idx = i * NTHR + tid;           // 0..511
        rowA[i] = idx >> 3; slotA[i] = idx & 7;
        srcA[i] = x + (size_t)(t0 + rowA[i]) * D_MODEL + slotA[i] * 4;
        rowB[i] = rowA[i]; slotB[i] = slotA[i];
        srcB[i] = gw + (size_t)rowB[i] * D_MODEL + slotB[i] * 4;
    }

    // ---- prologue: issue fills for chunks 0..2
#pragma unroll
    for (int c = 0; c < 3; c++) {
        const uint32_t st = sbase + (uint32_t)(c * STAGE_F * 4);
#pragma unroll
        for (int i = 0; i < 2; i++) {
            CPASYNC16(st + (uint32_t)((rowA[i] * PITCH + slotA[i] * 4) * 4),
                      srcA[i] + (size_t)c * KC);
            CPASYNC16(st + (uint32_t)((B_OFF + rowB[i] * PITCH + slotB[i] * 4) * 4),
                      srcB[i] + (size_t)c * KC);
        }
        CPCOMMIT();
    }

    float acc[2][4][4];
#pragma unroll
    for (int mi = 0; mi < 2; mi++)
#pragma unroll
        for (int ni = 0; ni < 4; ni++)
#pragma unroll
            for (int j = 0; j < 4; j++) acc[mi][ni][j] = 0.0f;

    // ---- main loop
    for (int c = 0; c < NCHUNK; c++) {
        CPWAIT2();                 // fill(c) complete (2 younger groups pending)
        __syncthreads();           // all warps past compute(c-1); data visible

        // issue fill(c+3) into buffer (c+3)%4 = (c-1)%4 (readers done)
        if (c + 3 < NCHUNK) {
            const uint32_t st = sbase + (uint32_t)(((c + 3) & 3) * STAGE_F * 4);
#pragma unroll
            for (int i = 0; i < 2; i++) {
                CPASYNC16(st + (uint32_t)((rowA[i] * PITCH + slotA[i] * 4) * 4),
                          srcA[i] + (size_t)(c + 3) * KC);
                CPASYNC16(st + (uint32_t)((B_OFF + rowB[i] * PITCH + slotB[i] * 4) * 4),
                          srcB[i] + (size_t)(c + 3) * KC);
            }
        }
        CPCOMMIT();                // unconditional: keeps pending-count invariant

        const uint32_t* su = (const uint32_t*)(dynsm + (c & 3) * STAGE_F);
#pragma unroll
        for (int ks = 0; ks < 2; ks++) {
            const int kc = kofs + ks * 8 + lc;
            uint32_t ah[2][4], al[2][4];
#pragma unroll
            for (int mi = 0; mi < 2; mi++) {
                int base = (wm * 32 + mi * 16 + lr) * PITCH + kc;
                uint32_t r0 = su[base];
                uint32_t r1 = su[base + 8 * PITCH];
                uint32_t r2 = su[base + 4];
                uint32_t r3 = su[base + 8 * PITCH + 4];
                SPLIT(r0, ah[mi][0], al[mi][0]);
                SPLIT(r1, ah[mi][1], al[mi][1]);
                SPLIT(r2, ah[mi][2], al[mi][2]);
                SPLIT(r3, ah[mi][3], al[mi][3]);
            }
#pragma unroll
            for (int ni = 0; ni < 4; ni++) {
                int bb = B_OFF + (wn * 32 + ni * 8 + lr) * PITCH + kc;
                uint32_t q0 = su[bb], q1 = su[bb + 4];
                uint32_t bh[2], bl[2];
                SPLIT(q0, bh[0], bl[0]);
                SPLIT(q1, bh[1], bl[1]);
#pragma unroll
                for (int mi = 0; mi < 2; mi++) {
                    MMA(acc[mi][ni], ah[mi], bh);
                    MMA(acc[mi][ni], al[mi], bh);
                    MMA(acc[mi][ni], ah[mi], bl);
                }
            }
        }
    }
    __syncthreads();   // all compute done before overlaying G

    // ---- merge warpgroup accumulators into G[64][65] (overlays stage smem)
    float* G = dynsm;
    if (wg == 0) {
#pragma unroll
        for (int mi = 0; mi < 2; mi++)
#pragma unroll
            for (int ni = 0; ni < 4; ni++) {
                int tr = wm * 32 + mi * 16 + lr;
                int ec = wn * 32 + ni * 8 + 2 * lc;
                G[tr * 65 + ec]           = acc[mi][ni][0];
                G[tr * 65 + ec + 1]       = acc[mi][ni][1];
                G[(tr + 8) * 65 + ec]     = acc[mi][ni][2];
                G[(tr + 8) * 65 + ec + 1] = acc[mi][ni][3];
            }
    }
    __syncthreads();
    if (wg == 1) {
#pragma unroll
        for (int mi = 0; mi < 2; mi++)
#pragma unroll
            for (int ni = 0; ni < 4; ni++) {
                int tr = wm * 32 + mi * 16 + lr;
                int ec = wn * 32 + ni * 8 + 2 * lc;
                G[tr * 65 + ec]           += acc[mi][ni][0];
                G[tr * 65 + ec + 1]       += acc[mi][ni][1];
                G[(tr + 8) * 65 + ec]     += acc[mi][ni][2];
                G[(tr + 8) * 65 + ec + 1] += acc[mi][ni][3];
            }
    }
    __syncthreads();

    // ---- epilogue phase 1: per-token max + top2 on logits
    int i1 = 0, i2 = 0;
    if (tid < TM) {
        const float* row = G + tid * 65;
        float v1 = -INFINITY, v2 = -INFINITY;
#pragma unroll 8
        for (int e = 0; e < N_EXP; e++) {
            float v = row[e];
            if (v > v1)      { v2 = v1; i2 = i1; v1 = v; i1 = e; }
            else if (v > v2) { v2 = v;  i2 = e; }
        }
        s_m[tid] = v1;   // max == top1
    }
    __syncthreads();

    // ---- phase 2: all 256 threads exponentiate (parallel MUFU)
#pragma unroll
    for (int i = 0; i < (TM * N_EXP) / NTHR; i++) {
        int idx = tid + i * NTHR;
        int t = idx >> 6, e = idx & 63;
        G[t * 65 + e] = expf(G[t * 65 + e] - s_m[t]);
    }
    __syncthreads();

    // ---- phase 3: per-token sums + outputs
    if (tid < TM) {
        const float* row = G + tid * 65;
        float ssum = 0.0f;
#pragma unroll 8
        for (int e = 0; e < N_EXP; e++) ssum += row[e];
        s_inv[tid] = 1.0f / ssum;

        float e1 = row[i1], e2 = row[i2];
        float rn = 1.0f / (e1 + e2);
        int tg = t0 + tid;
        out[2 * tg]     = e1 * rn;
        out[2 * tg + 1] = e2 * rn;
        out[2 * N_TOKENS + 2 * tg]     = (float)i1;
        out[2 * N_TOKENS + 2 * tg + 1] = (float)i2;
        atomicAdd(&cb[i1], 1);
    }
    __syncthreads();

    // ---- phase 4: per-expert prob sums -> global
    if (tid < N_EXP) {
        float s = 0.0f;
#pragma unroll 8
        for (int t = 0; t < TM; t++) s += G[t * 65 + tid] * s_inv[t];
        atomicAdd(&g_psum[tid], s);
        atomicAdd(&g_cnt[tid], cb[tid]);
    }

    // ---- last CTA: loss + scratch reset
    if (tid == 0) {
        __threadfence();
        int t = atomicAdd(&g_ticket, 1);
        s_islast = (t == NCTA - 1) ? 1 : 0;
    }
    __syncthreads();
    if (s_islast) {
        __threadfence();
        if (tid < N_EXP) {
            float p = *(volatile float*)&g_psum[tid];
            int   f = *(volatile int*)&g_cnt[tid];
            s_red[tid] = (float)f * p;
            g_psum[tid] = 0.0f;
            g_cnt[tid]  = 0;
        }
        __syncthreads();
        for (int st = 32; st > 0; st >>= 1) {
            if (tid < st) s_red[tid] += s_red[tid + st];
            __syncthreads();
        }
        if (tid == 0) {
            out[4 * N_TOKENS] = LB_COEF * s_red[0] * (1.0f / N_TOKENS) * (1.0f / N_TOKENS);
            g_ticket = 0;
        }
    }
}

// ---------------- launch ----------------
extern "C" void kernel_launch(void* const* d_in, const int* in_sizes, int n_in,
                              void* d_out, int out_size)
{
    const float* x  = (const float*)d_in[0];
    const float* gw = (const float*)d_in[1];
    float* out = (float*)d_out;

    cudaFuncSetAttribute(router_kernel,
                         cudaFuncAttributeMaxDynamicSharedMemorySize, DYN_BYTES);

    router_kernel<<<NCTA, NTHR, DYN_BYTES>>>(x, gw, out);
}

// round 10
// speedup vs baseline: 1.4313x; 1.1817x over previous
#include <cuda_runtime.h>
#include <cuda_fp16.h>
#include <math.h>
#include <stdint.h>

#define N_TOKENS 16384
#define D_MODEL  4096
#define N_EXP    64
#define LB_COEF  0.01f

#define KC     32                 // k per chunk (two 16-k warpgroup halves)
#define NCHUNK (D_MODEL / KC)     // 128
#define TM     64
#define NCTA   (N_TOKENS / TM)    // 256
#define NTHR   256

// stage layout in 32-bit words; each row = 16 f16x2 pair-words + 4 pad
#define PA      20
#define A1_OFF  0
#define A2_OFF  (64 * PA)          // 1280
#define B1_OFF  (2 * 64 * PA)      // 2560
#define B2_OFF  (3 * 64 * PA)      // 3840
#define STAGE_W (4 * 64 * PA)      // 5120 words = 20 KB
#define DYN_BYTES (2 * STAGE_W * 4)   // 40960 B (logits 64*65*4 fits)

#define WSCALE  256.0f
#define WDESCALE 0.00390625f       // 2^-8

// ---------------- helpers ----------------
// split float4 -> f16 hi pairs (h1) + f16 residual pairs (h2); exact 2-term split
static __device__ __forceinline__ void split4(float4 v, uint2& h1, uint2& h2) {
    __half a0 = __float2half_rn(v.x);
    __half a1 = __float2half_rn(v.y);
    __half a2 = __float2half_rn(v.z);
    __half a3 = __float2half_rn(v.w);
    __half b0 = __float2half_rn(v.x - __half2float(a0));
    __half b1 = __float2half_rn(v.y - __half2float(a1));
    __half b2 = __float2half_rn(v.z - __half2float(a2));
    __half b3 = __float2half_rn(v.w - __half2float(a3));
    __half2 p01 = __halves2half2(a0, a1);
    __half2 p23 = __halves2half2(a2, a3);
    __half2 q01 = __halves2half2(b0, b1);
    __half2 q23 = __halves2half2(b2, b3);
    h1.x = *reinterpret_cast<uint32_t*>(&p01);
    h1.y = *reinterpret_cast<uint32_t*>(&p23);
    h2.x = *reinterpret_cast<uint32_t*>(&q01);
    h2.y = *reinterpret_cast<uint32_t*>(&q23);
}

#define MMAH(d, a, b)                                                    \
    asm volatile(                                                        \
        "mma.sync.aligned.m16n8k16.row.col.f32.f16.f16.f32 "             \
        "{%0,%1,%2,%3}, {%4,%5,%6,%7}, {%8,%9}, {%0,%1,%2,%3};"          \
        : "+f"((d)[0]), "+f"((d)[1]), "+f"((d)[2]), "+f"((d)[3])         \
        : "r"((a)[0]), "r"((a)[1]), "r"((a)[2]), "r"((a)[3]),            \
          "r"((b)[0]), "r"((b)[1]))

// ---------------- device scratch (zero-initialized at module load) ----------------
__device__ float g_psum[N_EXP];
__device__ int   g_cnt[N_EXP];
__device__ int   g_ticket;

// ---------------- fused GEMM (2xFP16 4-term) + softmax/top2 + loss ----------------
// 256 threads = 8 warps, 2+ CTAs/SM. CTA tile 64x64. Warp tile 32x32 over one k16.
// wg (wid>>2) selects k-half of each 32-k chunk.
__global__ __launch_bounds__(NTHR, 2)
void router_kernel(const float* __restrict__ x,
                   const float* __restrict__ gw,
                   float* __restrict__ out)
{
    extern __shared__ float dynsm[];
    __shared__ int   cb[N_EXP];
    __shared__ float s_red[N_EXP];
    __shared__ float s_m[TM];
    __shared__ float s_inv[TM];
    __shared__ int   s_islast;

    const int tid  = threadIdx.x;
    const int t0   = blockIdx.x * TM;
    const int lane = tid & 31;
    const int wid  = tid >> 5;
    const int wg   = wid >> 2;          // k16-half of chunk
    const int widg = wid & 3;
    const int wm   = widg >> 1;         // 0..1 -> token base wm*32
    const int wn   = widg & 1;          // 0..1 -> expert base wn*32
    const int lr   = lane >> 2;
    const int lc   = lane & 3;
    const int kp   = wg * 8 + lc;       // pair-word base within row

    if (tid < N_EXP) cb[tid] = 0;

    uint32_t* smw = (uint32_t*)dynsm;

    // fill mapping: row r = tid>>2 (0..63), f4 slots s and s+4
    const int rA = tid >> 2;
    const int sA = tid & 3;

    const float4* x4 = (const float4*)x;     // row pitch 1024 f4
    const float4* w4 = (const float4*)gw;

    const size_t xo = (size_t)(t0 + rA) * 1024 + sA;
    const size_t wo = (size_t)rA        * 1024 + sA;

    float4 va0, va1, vb0, vb1;

    // ---- prologue: chunk 0 -> stage 0
    va0 = x4[xo]; va1 = x4[xo + 4];
    vb0 = w4[wo]; vb1 = w4[wo + 4];
    {
        uint32_t* s = smw;
        uint2 h1, h2;
        split4(va0, h1, h2);
        *(uint2*)(s + A1_OFF + rA * PA + 2 * sA) = h1;
        *(uint2*)(s + A2_OFF + rA * PA + 2 * sA) = h2;
        split4(va1, h1, h2);
        *(uint2*)(s + A1_OFF + rA * PA + 2 * sA + 8) = h1;
        *(uint2*)(s + A2_OFF + rA * PA + 2 * sA + 8) = h2;
        split4(make_float4(vb0.x * WSCALE, vb0.y * WSCALE, vb0.z * WSCALE, vb0.w * WSCALE), h1, h2);
        *(uint2*)(s + B1_OFF + rA * PA + 2 * sA) = h1;
        *(uint2*)(s + B2_OFF + rA * PA + 2 * sA) = h2;
        split4(make_float4(vb1.x * WSCALE, vb1.y * WSCALE, vb1.z * WSCALE, vb1.w * WSCALE), h1, h2);
        *(uint2*)(s + B1_OFF + rA * PA + 2 * sA + 8) = h1;
        *(uint2*)(s + B2_OFF + rA * PA + 2 * sA + 8) = h2;
    }
    __syncthreads();

    float acc[2][4][4];
#pragma unroll
    for (int mi = 0; mi < 2; mi++)
#pragma unroll
        for (int ni = 0; ni < 4; ni++)
#pragma unroll
            for (int j = 0; j < 4; j++) acc[mi][ni][j] = 0.0f;

    // ---- main loop: double-buffered, one bar per chunk
    for (int c = 0; c < NCHUNK; c++) {
        if (c + 1 < NCHUNK) {
            const size_t d = (size_t)(c + 1) * 8;
            va0 = x4[xo + d]; va1 = x4[xo + d + 4];
            vb0 = w4[wo + d]; vb1 = w4[wo + d + 4];
        }

        // compute on current stage (one k16 per warp)
        {
            const uint32_t* s = smw + (c & 1) * STAGE_W;
            uint32_t a1[2][4], a2[2][4];
#pragma unroll
            for (int mi = 0; mi < 2; mi++) {
                int ar = (wm * 32 + mi * 16 + lr) * PA + kp;
                a1[mi][0] = s[A1_OFF + ar];
                a1[mi][1] = s[A1_OFF + ar + 8 * PA];
                a1[mi][2] = s[A1_OFF + ar + 4];
                a1[mi][3] = s[A1_OFF + ar + 8 * PA + 4];
                a2[mi][0] = s[A2_OFF + ar];
                a2[mi][1] = s[A2_OFF + ar + 8 * PA];
                a2[mi][2] = s[A2_OFF + ar + 4];
                a2[mi][3] = s[A2_OFF + ar + 8 * PA + 4];
            }
#pragma unroll
            for (int ni = 0; ni < 4; ni++) {
                int br = (wn * 32 + ni * 8 + lr) * PA + kp;
                uint32_t b1[2] = { s[B1_OFF + br], s[B1_OFF + br + 4] };
                uint32_t b2[2] = { s[B2_OFF + br], s[B2_OFF + br + 4] };
#pragma unroll
                for (int mi = 0; mi < 2; mi++) {
                    MMAH(acc[mi][ni], a1[mi], b1);
                    MMAH(acc[mi][ni], a2[mi], b1);
                    MMAH(acc[mi][ni], a1[mi], b2);
                    MMAH(acc[mi][ni], a2[mi], b2);
                }
            }
        }

        // convert + store chunk c+1 into the other stage
        if (c + 1 < NCHUNK) {
            uint32_t* s = smw + ((c + 1) & 1) * STAGE_W;
            uint2 h1, h2;
            split4(va0, h1, h2);
            *(uint2*)(s + A1_OFF + rA * PA + 2 * sA) = h1;
            *(uint2*)(s + A2_OFF + rA * PA + 2 * sA) = h2;
            split4(va1, h1, h2);
            *(uint2*)(s + A1_OFF + rA * PA + 2 * sA + 8) = h1;
            *(uint2*)(s + A2_OFF + rA * PA + 2 * sA + 8) = h2;
            split4(make_float4(vb0.x * WSCALE, vb0.y * WSCALE, vb0.z * WSCALE, vb0.w * WSCALE), h1, h2);
            *(uint2*)(s + B1_OFF + rA * PA + 2 * sA) = h1;
            *(uint2*)(s + B2_OFF + rA * PA + 2 * sA) = h2;
            split4(make_float4(vb1.x * WSCALE, vb1.y * WSCALE, vb1.z * WSCALE, vb1.w * WSCALE), h1, h2);
            *(uint2*)(s + B1_OFF + rA * PA + 2 * sA + 8) = h1;
            *(uint2*)(s + B2_OFF + rA * PA + 2 * sA + 8) = h2;
        }
        __syncthreads();
    }

    // ---- merge k-half accumulators into G[64][65] (overlays stage smem)
    float* G = dynsm;
    if (wg == 0) {
#pragma unroll
        for (int mi = 0; mi < 2; mi++)
#pragma unroll
            for (int ni = 0; ni < 4; ni++) {
                int tr = wm * 32 + mi * 16 + lr;
                int ec = wn * 32 + ni * 8 + 2 * lc;
                G[tr * 65 + ec]           = acc[mi][ni][0] * WDESCALE;
                G[tr * 65 + ec + 1]       = acc[mi][ni][1] * WDESCALE;
                G[(tr + 8) * 65 + ec]     = acc[mi][ni][2] * WDESCALE;
                G[(tr + 8) * 65 + ec + 1] = acc[mi][ni][3] * WDESCALE;
            }
    }
    __syncthreads();
    if (wg == 1) {
#pragma unroll
        for (int mi = 0; mi < 2; mi++)
#pragma unroll
            for (int ni = 0; ni < 4; ni++) {
                int tr = wm * 32 + mi * 16 + lr;
                int ec = wn * 32 + ni * 8 + 2 * lc;
                G[tr * 65 + ec]           += acc[mi][ni][0] * WDESCALE;
                G[tr * 65 + ec + 1]       += acc[mi][ni][1] * WDESCALE;
                G[(tr + 8) * 65 + ec]     += acc[mi][ni][2] * WDESCALE;
                G[(tr + 8) * 65 + ec + 1] += acc[mi][ni][3] * WDESCALE;
            }
    }
    __syncthreads();

    // ---- epilogue phase 1: per-token max + top2 on logits
    int i1 = 0, i2 = 0;
    if (tid < TM) {
        const float* row = G + tid * 65;
        float v1 = -INFINITY, v2 = -INFINITY;
#pragma unroll 8
        for (int e = 0; e < N_EXP; e++) {
            float v = row[e];
            if (v > v1)      { v2 = v1; i2 = i1; v1 = v; i1 = e; }
            else if (v > v2) { v2 = v;  i2 = e; }
        }
        s_m[tid] = v1;   // max == top1
    }
    __syncthreads();

    // ---- phase 2: all 256 threads exponentiate (parallel MUFU)
#pragma unroll
    for (int i = 0; i < (TM * N_EXP) / NTHR; i++) {
        int idx = tid + i * NTHR;
        int t = idx >> 6, e = idx & 63;
        G[t * 65 + e] = expf(G[t * 65 + e] - s_m[t]);
    }
    __syncthreads();

    // ---- phase 3: per-token sums + outputs
    if (tid < TM) {
        const float* row = G + tid * 65;
        float ssum = 0.0f;
#pragma unroll 8
        for (int e = 0; e < N_EXP; e++) ssum += row[e];
        s_inv[tid] = 1.0f / ssum;

        float e1 = row[i1], e2 = row[i2];
        float rn = 1.0f / (e1 + e2);
        int tg = t0 + tid;
        out[2 * tg]     = e1 * rn;
        out[2 * tg + 1] = e2 * rn;
        out[2 * N_TOKENS + 2 * tg]     = (float)i1;
        out[2 * N_TOKENS + 2 * tg + 1] = (float)i2;
        atomicAdd(&cb[i1], 1);
    }
    __syncthreads();

    // ---- phase 4: per-expert prob sums -> global
    if (tid < N_EXP) {
        float s = 0.0f;
#pragma unroll 8
        for (int t = 0; t < TM; t++) s += G[t * 65 + tid] * s_inv[t];
        atomicAdd(&g_psum[tid], s);
        atomicAdd(&g_cnt[tid], cb[tid]);
    }

    // ---- last CTA: loss + scratch reset
    if (tid == 0) {
        __threadfence();
        int t = atomicAdd(&g_ticket, 1);
        s_islast = (t == NCTA - 1) ? 1 : 0;
    }
    __syncthreads();
    if (s_islast) {
        __threadfence();
        if (tid < N_EXP) {
            float p = *(volatile float*)&g_psum[tid];
            int   f = *(volatile int*)&g_cnt[tid];
            s_red[tid] = (float)f * p;
            g_psum[tid] = 0.0f;
            g_cnt[tid]  = 0;
        }
        __syncthreads();
        for (int st = 32; st > 0; st >>= 1) {
            if (tid < st) s_red[tid] += s_red[tid + st];
            __syncthreads();
        }
        if (tid == 0) {
            out[4 * N_TOKENS] = LB_COEF * s_red[0] * (1.0f / N_TOKENS) * (1.0f / N_TOKENS);
            g_ticket = 0;
        }
    }
}

// ---------------- launch ----------------
extern "C" void kernel_launch(void* const* d_in, const int* in_sizes, int n_in,
                              void* d_out, int out_size)
{
    const float* x  = (const float*)d_in[0];
    const float* gw = (const float*)d_in[1];
    float* out = (float*)d_out;

    cudaFuncSetAttribute(router_kernel,
                         cudaFuncAttributeMaxDynamicSharedMemorySize, DYN_BYTES);

    router_kernel<<<NCTA, NTHR, DYN_BYTES>>>(x, gw, out);
}